// round 16
// baseline (speedup 1.0000x reference)
#include <cuda_runtime.h>
#include <cuda_bf16.h>
#include <cstdint>

constexpr int cV = 32000, cH = 1024, cB = 32, cT = 64;
constexpr int cM = cB * cT;           // 2048
constexpr int cG = 3 * cH;            // 3072
constexpr long long cBTV = (long long)cB * cT * cV;

constexpr int NCTA = 128;             // recurrence CTAs
constexpr int UPC  = 8;               // hidden units per CTA
constexpr int RTHREADS = 192;         // 6 warps: (gate, m-half)

__device__ __align__(16) unsigned      g_X[cM * cH];             // tf32 relu(embed)
__device__ __align__(16) unsigned      g_wihtf[(size_t)cG * cH]; // tf32 w_ih
__device__ __align__(16) float         g_gi[(size_t)cM * cG];
__device__ __align__(16) unsigned      g_htf[2][cB * cH];        // tf32 h ping-pong
__device__ __align__(16) __nv_bfloat16 g_hsb[cM * cH];           // [b*T+t][H]
__device__ __align__(16) __nv_bfloat16 g_wob[(size_t)cV * cH];
__device__ float g_sum[cM];
__device__ unsigned g_flags[NCTA * 32];   // 128B-strided barrier slots

__device__ __forceinline__ unsigned f2tf(float f) {
    unsigned u; asm("cvt.rna.tf32.f32 %0, %1;" : "=r"(u) : "f"(f)); return u;
}
__device__ __forceinline__ unsigned smem_u32(const void* p) {
    unsigned a;
    asm("{ .reg .u64 t; cvta.to.shared.u64 t, %1; cvt.u32.u64 %0, t; }" : "=r"(a) : "l"(p));
    return a;
}
__device__ __forceinline__ void mma_tf32(float* c, const unsigned* a, unsigned b0, unsigned b1) {
    asm volatile("mma.sync.aligned.m16n8k8.row.col.f32.tf32.tf32.f32 "
        "{%0,%1,%2,%3}, {%4,%5,%6,%7}, {%8,%9}, {%0,%1,%2,%3};\n"
        : "+f"(c[0]), "+f"(c[1]), "+f"(c[2]), "+f"(c[3])
        : "r"(a[0]), "r"(a[1]), "r"(a[2]), "r"(a[3]), "r"(b0), "r"(b1));
}
__device__ __forceinline__ void mma_bf16(float* c, const unsigned* a, unsigned b0, unsigned b1) {
    asm volatile("mma.sync.aligned.m16n8k16.row.col.f32.bf16.bf16.f32 "
        "{%0,%1,%2,%3}, {%4,%5,%6,%7}, {%8,%9}, {%0,%1,%2,%3};\n"
        : "+f"(c[0]), "+f"(c[1]), "+f"(c[2]), "+f"(c[3])
        : "r"(a[0]), "r"(a[1]), "r"(a[2]), "r"(a[3]), "r"(b0), "r"(b1));
}
__device__ __forceinline__ void ldmat4(unsigned* r, unsigned addr) {
    asm volatile("ldmatrix.sync.aligned.m8n8.x4.shared.b16 {%0,%1,%2,%3}, [%4];"
        : "=r"(r[0]), "=r"(r[1]), "=r"(r[2]), "=r"(r[3]) : "r"(addr));
}
__device__ __forceinline__ void cpasync16(unsigned dst, const void* src) {
    asm volatile("cp.async.cg.shared.global [%0], [%1], 16;\n" :: "r"(dst), "l"(src));
}

// ---- K0: fused preamble (w_out conversion moved into k_rnn) ------------------
// blocks [0, cG)          : w_ih -> tf32
// blocks [cG, cG+cM)      : relu(embedding[token]) -> g_X
// blocks [cG+cM, +128)    : h0 -> tf32, reset sums/flags
__global__ void k_pre(const int* __restrict__ target, const float* __restrict__ emb,
                      const float* __restrict__ w_ih, const float* __restrict__ h0) {
    int bx = blockIdx.x;
    if (bx < cG) {
        size_t i = (size_t)bx * 1024 + threadIdx.x * 4;
        float4 v = *(const float4*)(w_ih + i);
        uint4 o; o.x = f2tf(v.x); o.y = f2tf(v.y); o.z = f2tf(v.z); o.w = f2tf(v.w);
        *(uint4*)(g_wihtf + i) = o;
    } else if (bx < cG + cM) {
        int m = bx - cG, t = m >> 5, b = m & 31;
        int tok = (t == 0) ? 1 : target[b * cT + (t - 1)];
        float4 v = ((const float4*)(emb + (size_t)tok * cH))[threadIdx.x];
        uint4 o;
        o.x = f2tf(fmaxf(v.x, 0.f)); o.y = f2tf(fmaxf(v.y, 0.f));
        o.z = f2tf(fmaxf(v.z, 0.f)); o.w = f2tf(fmaxf(v.w, 0.f));
        ((uint4*)(g_X + (size_t)m * cH))[threadIdx.x] = o;
    } else {
        int i = (bx - cG - cM) * 256 + threadIdx.x;
        g_htf[0][i] = f2tf(h0[i]);
        if (i < cM) g_sum[i] = 0.f;
        if (i < NCTA * 32) g_flags[i] = 0;
    }
}

// ---- K2: gi = X @ w_ih^T + b_ih (tf32, 128x128 tile, 3-stage, 2 CTA/SM) ------
constexpr int GKCH = 32;
constexpr int GPAD = 36;
constexpr int GSTG = 128 * GPAD * 4;       // 18432 B
constexpr int GSM_TOT = 6 * GSTG + 16;

__global__ __launch_bounds__(256, 2) void k_gi(const float* __restrict__ bih) {
    extern __shared__ char smg[];
    const unsigned smb = smem_u32(smg);
    const unsigned aBase = smb, bBase = smb + 3 * GSTG;
    const int m0 = blockIdx.x * 128, n0 = blockIdx.y * 128;
    const int tid = threadIdx.x, lane = tid & 31;
    const int w = tid >> 5, wm = w & 1, wn = w >> 1;
    const int g = lane >> 2, q = lane & 3;

    float acc[4][4][4];
#pragma unroll
    for (int a = 0; a < 4; a++)
#pragma unroll
        for (int b = 0; b < 4; b++)
#pragma unroll
            for (int c = 0; c < 4; c++) acc[a][b][c] = 0.f;

    auto loadStage = [&](int s) {
        int buf = s % 3;
        const char* asrc = (const char*)(g_X + (size_t)m0 * cH + s * GKCH);
        const char* bsrc = (const char*)(g_wihtf + (size_t)n0 * cH + s * GKCH);
        unsigned ad = aBase + buf * GSTG, bd = bBase + buf * GSTG;
#pragma unroll
        for (int j = 0; j < 4; ++j) {
            int i = tid + 256 * j;
            int row = i >> 3, cb = (i & 7) * 16;
            cpasync16(ad + row * (GPAD * 4) + cb, asrc + (size_t)row * (cH * 4) + cb);
            cpasync16(bd + row * (GPAD * 4) + cb, bsrc + (size_t)row * (cH * 4) + cb);
        }
        asm volatile("cp.async.commit_group;\n");
    };

    loadStage(0); loadStage(1);
    constexpr int NS = cH / GKCH;   // 32
    for (int s = 0; s < NS; ++s) {
        if (s == NS - 1) asm volatile("cp.async.wait_group 0;\n");
        else             asm volatile("cp.async.wait_group 1;\n");
        __syncthreads();
        if (s + 2 < NS) loadStage(s + 2);
        int buf = s % 3;
        const unsigned* aS = (const unsigned*)(smg + buf * GSTG);
        const unsigned* bS = (const unsigned*)(smg + 3 * GSTG + buf * GSTG);
#pragma unroll
        for (int kt = 0; kt < 4; ++kt) {
            int kk = kt * 8;
            unsigned a[4][4];
#pragma unroll
            for (int mt = 0; mt < 4; ++mt) {
                int r = wm * 64 + mt * 16 + g;
                a[mt][0] = aS[r * GPAD + kk + q];
                a[mt][1] = aS[(r + 8) * GPAD + kk + q];
                a[mt][2] = aS[r * GPAD + kk + q + 4];
                a[mt][3] = aS[(r + 8) * GPAD + kk + q + 4];
            }
#pragma unroll
            for (int nt = 0; nt < 4; ++nt) {
                int c = wn * 32 + nt * 8 + g;
                unsigned b0 = bS[c * GPAD + kk + q];
                unsigned b1 = bS[c * GPAD + kk + q + 4];
#pragma unroll
                for (int mt = 0; mt < 4; ++mt)
                    mma_tf32(acc[mt][nt], a[mt], b0, b1);
            }
        }
    }
#pragma unroll
    for (int mt = 0; mt < 4; ++mt)
#pragma unroll
        for (int nt = 0; nt < 4; ++nt) {
            int row = m0 + wm * 64 + mt * 16 + g;
            int col = n0 + wn * 32 + nt * 8 + 2 * q;
            float b0 = bih[col], b1 = bih[col + 1];
            g_gi[(size_t)row * cG + col]           = acc[mt][nt][0] + b0;
            g_gi[(size_t)row * cG + col + 1]       = acc[mt][nt][1] + b1;
            g_gi[(size_t)(row + 8) * cG + col]     = acc[mt][nt][2] + b0;
            g_gi[(size_t)(row + 8) * cG + col + 1] = acc[mt][nt][3] + b1;
        }
}

// ---- K3: persistent GRU recurrence (tf32, 192 threads, single acc chain) -----
// Also strip-mines w_out -> bf16 conversion into the barrier dead time.
constexpr int WSTR = 1028;
constexpr int HSTR = 260;     // 256 + 4 pad words

__global__ __launch_bounds__(RTHREADS) void k_rnn(const float* __restrict__ h0,
                                                  const float* __restrict__ Whh,
                                                  const float* __restrict__ bhh,
                                                  const float* __restrict__ w_out,
                                                  float* __restrict__ outh) {
    extern __shared__ unsigned su[];
    unsigned* w_s  = su;                        // 24 * WSTR
    unsigned* h_s  = w_s + 24 * WSTR;           // 3 * 32 * HSTR
    float*    sGH  = (float*)(h_s + 3 * 32 * HSTR);
    float*    h_own = sGH + 3 * 32 * 9;
    float*    bhh_s = h_own + 32 * 8;

    const int tid = threadIdx.x, lane = tid & 31, w = tid >> 5;
    const int gate = w >> 1, mh = w & 1;        // warp = (gate, m-half)
    const int g = lane >> 2, q = lane & 3;
    const int u0 = blockIdx.x * UPC;

    for (int i = tid; i < 24 * 256; i += RTHREADS) {
        int r = i >> 8, c4 = (i & 255) * 4;
        int gt = r >> 3, rr = r & 7;
        float4 v = *(const float4*)(Whh + ((size_t)gt * cH + u0 + rr) * cH + c4);
        unsigned* p = &w_s[r * WSTR + c4];
        p[0] = f2tf(v.x); p[1] = f2tf(v.y); p[2] = f2tf(v.z); p[3] = f2tf(v.w);
    }
    if (tid < 24) bhh_s[tid] = bhh[(tid >> 3) * cH + u0 + (tid & 7)];
    for (int i = tid; i < 32 * 8; i += RTHREADS)
        h_own[i] = h0[(i >> 3) * cH + u0 + (i & 7)];
    __syncthreads();

    for (int t = 0; t < cT; ++t) {
        float gr[2], gz[2], gn[2];
#pragma unroll
        for (int j = 0; j < 2; ++j) {
            int idx = tid + RTHREADS * j;
            if (idx < 256) {
                int b = idx >> 3, u = idx & 7;
                const float* gi = g_gi + ((size_t)t * cB + b) * cG + u0 + u;
                gr[j] = gi[0]; gz[j] = gi[cH]; gn[j] = gi[2 * cH];
            }
        }
        const unsigned* hsrc = g_htf[t & 1];
        auto ldchunk = [&](int ki) {
            int buf = ki % 3, kc = ki * 256;
            for (int i = tid; i < 2048; i += RTHREADS) {   // 32 rows x 64 uint4
                int r = i >> 6, c4 = (i & 63) * 4;
                cpasync16(smem_u32(&h_s[buf * 32 * HSTR + r * HSTR + c4]),
                          hsrc + r * cH + kc + c4);
            }
            asm volatile("cp.async.commit_group;\n");
        };
        ldchunk(0); ldchunk(1);
        float acc[4] = {0.f, 0.f, 0.f, 0.f};
        for (int ki = 0; ki < 4; ++ki) {
            if (ki == 3) asm volatile("cp.async.wait_group 0;\n");
            else         asm volatile("cp.async.wait_group 1;\n");
            __syncthreads();
            if (ki + 2 < 4) ldchunk(ki + 2);
            const unsigned* hb = &h_s[(ki % 3) * 32 * HSTR];
            const unsigned* wb = &w_s[gate * 8 * WSTR + ki * 256];
#pragma unroll
            for (int kk = 0; kk < 32; ++kk) {
                int kcol = kk * 8;
                unsigned b0 = wb[g * WSTR + kcol + q];
                unsigned b1 = wb[g * WSTR + kcol + q + 4];
                unsigned a[4];
                a[0] = hb[(mh * 16 + g) * HSTR + kcol + q];
                a[1] = hb[(mh * 16 + g + 8) * HSTR + kcol + q];
                a[2] = hb[(mh * 16 + g) * HSTR + kcol + q + 4];
                a[3] = hb[(mh * 16 + g + 8) * HSTR + kcol + q + 4];
                mma_tf32(acc, a, b0, b1);
            }
        }
        __syncthreads();
        float* sg = sGH + gate * (32 * 9);
        sg[(mh * 16 + g) * 9 + 2 * q]         = acc[0];
        sg[(mh * 16 + g) * 9 + 2 * q + 1]     = acc[1];
        sg[(mh * 16 + g + 8) * 9 + 2 * q]     = acc[2];
        sg[(mh * 16 + g + 8) * 9 + 2 * q + 1] = acc[3];
        __syncthreads();
#pragma unroll
        for (int j = 0; j < 2; ++j) {
            int idx = tid + RTHREADS * j;
            if (idx < 256) {
                int b = idx >> 3, u = idx & 7;
                float pr = gr[j] + sGH[0 * 288 + b * 9 + u] + bhh_s[u];
                float pz = gz[j] + sGH[1 * 288 + b * 9 + u] + bhh_s[8 + u];
                float hn = sGH[2 * 288 + b * 9 + u] + bhh_s[16 + u];
                float r = 1.f / (1.f + expf(-pr));
                float z = 1.f / (1.f + expf(-pz));
                float n = tanhf(gn[j] + r * hn);
                float hv = (1.f - z) * n + z * h_own[idx];
                h_own[idx] = hv;
                g_htf[(t + 1) & 1][b * cH + u0 + u] = f2tf(hv);
                g_hsb[((size_t)b * cT + t) * cH + u0 + u] = __float2bfloat16(hv);
                if (t == cT - 1) outh[b * cH + u0 + u] = hv;
            }
        }
        __threadfence();
        __syncthreads();
        if (tid == 0) ((volatile unsigned*)g_flags)[blockIdx.x * 32] = t + 1;
        // strip-mined w_out -> bf16 conversion in barrier dead time:
        // CTA owns float4s [bx*64000, (bx+1)*64000); this step does 1000 of them.
        {
            size_t base4 = (size_t)blockIdx.x * 64000 + (size_t)t * 1000;
            for (int i = tid; i < 1000; i += RTHREADS) {
                float4 v = ((const float4*)w_out)[base4 + i];
                __nv_bfloat162* dst = (__nv_bfloat162*)g_wob + (base4 + i) * 2;
                dst[0] = __floats2bfloat162_rn(v.x, v.y);
                dst[1] = __floats2bfloat162_rn(v.z, v.w);
            }
        }
        if (tid < NCTA)
            while (((volatile unsigned*)g_flags)[tid * 32] < (unsigned)(t + 1)) { }
        __syncthreads();
        __threadfence();
    }
}

// ---- K4: logits GEMM (bf16 HMMA, 128x128, 3-stage cp.async, 2 CTA/SM) --------
constexpr int LKCH = 64;
constexpr int LPAD = 72;
constexpr int LSTG = 128 * LPAD * 2;      // 18432 B
constexpr int LSM_TOT = 6 * LSTG + 1024;

__global__ __launch_bounds__(256, 2) void k_logits(const float* __restrict__ bout,
                                                   float* __restrict__ out) {
    extern __shared__ char sm[];
    const unsigned smb = smem_u32(sm);
    const unsigned aBase = smb, bBase = smb + 3 * LSTG;
    float* srow  = (float*)(sm + 6 * LSTG);
    float* sbias = srow + 128;
    const int m0 = blockIdx.x * 128, n0 = blockIdx.y * 128;
    const int tid = threadIdx.x, lane = tid & 31;
    const int w = tid >> 5, wm = w & 1, wn = w >> 1;
    const int g = lane >> 2, q = lane & 3;
    const int lr = lane & 7, lh = (lane >> 3) & 1, lq = lane >> 4;
    const int arow = lr + lh * 8, acol = lq * 8;
    const int brow = lr + lq * 8, bcol = lh * 8;

    if (tid < 128) { srow[tid] = 0.f; sbias[tid] = bout[n0 + tid]; }

    float acc[4][4][4];
#pragma unroll
    for (int a = 0; a < 4; a++)
#pragma unroll
        for (int b = 0; b < 4; b++)
#pragma unroll
            for (int c = 0; c < 4; c++) acc[a][b][c] = 0.f;

    auto loadStage = [&](int s) {
        int buf = s % 3;
        const char* asrc = (const char*)(g_hsb + (size_t)m0 * cH + s * LKCH);
        const char* bsrc = (const char*)(g_wob + (size_t)n0 * cH + s * LKCH);
        unsigned ad = aBase + buf * LSTG, bd = bBase + buf * LSTG;
#pragma unroll
        for (int j = 0; j < 4; ++j) {
            int i = tid + 256 * j;
            int row = i >> 3, cb = (i & 7) * 16;
            cpasync16(ad + row * (LPAD * 2) + cb, asrc + (size_t)row * (cH * 2) + cb);
            cpasync16(bd + row * (LPAD * 2) + cb, bsrc + (size_t)row * (cH * 2) + cb);
        }
        asm volatile("cp.async.commit_group;\n");
    };

    loadStage(0); loadStage(1);
    constexpr int NS = cH / LKCH;   // 16
    for (int s = 0; s < NS; ++s) {
        if (s == NS - 1) asm volatile("cp.async.wait_group 0;\n");
        else             asm volatile("cp.async.wait_group 1;\n");
        __syncthreads();
        if (s + 2 < NS) loadStage(s + 2);
        int buf = s % 3;
        unsigned aS = aBase + buf * LSTG, bS = bBase + buf * LSTG;
#pragma unroll
        for (int kt = 0; kt < 4; ++kt) {
            int kk = kt * 16;
            unsigned a[4][4], bf[2][4];
#pragma unroll
            for (int mt = 0; mt < 4; ++mt)
                ldmat4(a[mt], aS + (((wm * 64 + mt * 16 + arow) * LPAD + kk + acol) << 1));
#pragma unroll
            for (int p = 0; p < 2; ++p)
                ldmat4(bf[p], bS + (((wn * 32 + p * 16 + brow) * LPAD + kk + bcol) << 1));
#pragma unroll
            for (int nt = 0; nt < 4; ++nt) {
                unsigned b0 = bf[nt >> 1][(nt & 1) * 2];
                unsigned b1 = bf[nt >> 1][(nt & 1) * 2 + 1];
#pragma unroll
                for (int mt = 0; mt < 4; ++mt)
                    mma_bf16(acc[mt][nt], a[mt], b0, b1);
            }
        }
    }

    float es[4][2];
#pragma unroll
    for (int mt = 0; mt < 4; ++mt) { es[mt][0] = 0.f; es[mt][1] = 0.f; }
#pragma unroll
    for (int mt = 0; mt < 4; ++mt)
#pragma unroll
        for (int nt = 0; nt < 4; ++nt) {
            int row = m0 + wm * 64 + mt * 16 + g;
            int lc  = wn * 32 + nt * 8 + 2 * q;
            int col = n0 + lc;
            float v0 = acc[mt][nt][0] + sbias[lc];
            float v1 = acc[mt][nt][1] + sbias[lc + 1];
            float v2 = acc[mt][nt][2] + sbias[lc];
            float v3 = acc[mt][nt][3] + sbias[lc + 1];
            out[(size_t)row * cV + col]           = v0;
            out[(size_t)row * cV + col + 1]       = v1;
            out[(size_t)(row + 8) * cV + col]     = v2;
            out[(size_t)(row + 8) * cV + col + 1] = v3;
            es[mt][0] += __expf(v0) + __expf(v1);
            es[mt][1] += __expf(v2) + __expf(v3);
        }
#pragma unroll
    for (int mt = 0; mt < 4; ++mt)
#pragma unroll
        for (int h = 0; h < 2; ++h) {
            es[mt][h] += __shfl_xor_sync(0xFFFFFFFFu, es[mt][h], 1);
            es[mt][h] += __shfl_xor_sync(0xFFFFFFFFu, es[mt][h], 2);
        }
    if (q == 0) {
#pragma unroll
        for (int mt = 0; mt < 4; ++mt) {
            atomicAdd(&srow[wm * 64 + mt * 16 + g], es[mt][0]);
            atomicAdd(&srow[wm * 64 + mt * 16 + g + 8], es[mt][1]);
        }
    }
    __syncthreads();
    if (tid < 128) atomicAdd(&g_sum[m0 + tid], srow[tid]);
}

// ---- K6: subtract log(sum) in-place (8 CTAs per row) -------------------------
__global__ __launch_bounds__(256) void k_sub(float* __restrict__ out) {
    int row = blockIdx.x;
    float l = logf(g_sum[row]);
    const int seg = blockIdx.y;              // 0..7, 4000 elems each
    float4* p = (float4*)(out + (size_t)row * cV + seg * 4000);
    for (int i = threadIdx.x; i < 1000; i += 256) {
        float4 v = p[i];
        v.x -= l; v.y -= l; v.z -= l; v.w -= l;
        p[i] = v;
    }
}

extern "C" void kernel_launch(void* const* d_in, const int* in_sizes, int n_in,
                              void* d_out, int out_size) {
    const float* enc_hidden = (const float*)d_in[1];
    const int*   target     = (const int*)d_in[2];
    const float* emb        = (const float*)d_in[3];
    const float* w_ih       = (const float*)d_in[4];
    const float* w_hh       = (const float*)d_in[5];
    const float* b_ih       = (const float*)d_in[6];
    const float* b_hh       = (const float*)d_in[7];
    const float* w_out      = (const float*)d_in[8];
    const float* b_out      = (const float*)d_in[9];
    float* out = (float*)d_out;

    constexpr int RSMEM = (24 * WSTR + 3 * 32 * HSTR) * 4 + (3 * 32 * 9 + 32 * 8 + 24) * 4;
    cudaFuncSetAttribute(k_rnn, cudaFuncAttributeMaxDynamicSharedMemorySize, RSMEM);
    cudaFuncSetAttribute(k_logits, cudaFuncAttributeMaxDynamicSharedMemorySize, LSM_TOT);
    cudaFuncSetAttribute(k_gi, cudaFuncAttributeMaxDynamicSharedMemorySize, GSM_TOT);

    k_pre<<<cG + cM + cB * cH / 256, 256>>>(target, emb, w_ih, enc_hidden);
    k_gi<<<dim3(cM / 128, cG / 128), 256, GSM_TOT>>>(b_ih);
    k_rnn<<<NCTA, RTHREADS, RSMEM>>>(enc_hidden, w_hh, b_hh, w_out, out + cBTV);
    k_logits<<<dim3(cM / 128, cV / 128), 256, LSM_TOT>>>(b_out, out);
    k_sub<<<dim3(cM, 8), 256>>>(out);
}

// round 17
// speedup vs baseline: 1.1219x; 1.1219x over previous
#include <cuda_runtime.h>
#include <cuda_bf16.h>
#include <cstdint>

constexpr int cV = 32000, cH = 1024, cB = 32, cT = 64;
constexpr int cM = cB * cT;           // 2048
constexpr int cG = 3 * cH;            // 3072
constexpr long long cBTV = (long long)cB * cT * cV;

constexpr int NCTA = 128;             // recurrence CTAs
constexpr int UPC  = 8;               // hidden units per CTA
constexpr int RTHREADS = 192;         // 6 warps: (gate, m-half)

__device__ __align__(16) unsigned      g_X[cM * cH];             // tf32 relu(embed)
__device__ __align__(16) unsigned      g_wihtf[(size_t)cG * cH]; // tf32 w_ih
__device__ __align__(16) float         g_gi[(size_t)cM * cG];
__device__ __align__(16) unsigned      g_htf[2][cB * cH];        // tf32 h ping-pong
__device__ __align__(16) __nv_bfloat16 g_hsb[cM * cH];           // [b*T+t][H]
__device__ __align__(16) __nv_bfloat16 g_wob[(size_t)cV * cH];
__device__ float g_sum[cM];
__device__ unsigned g_flags[NCTA * 32];   // 128B-strided barrier slots

__device__ __forceinline__ unsigned f2tf(float f) {
    unsigned u; asm("cvt.rna.tf32.f32 %0, %1;" : "=r"(u) : "f"(f)); return u;
}
__device__ __forceinline__ unsigned smem_u32(const void* p) {
    unsigned a;
    asm("{ .reg .u64 t; cvta.to.shared.u64 t, %1; cvt.u32.u64 %0, t; }" : "=r"(a) : "l"(p));
    return a;
}
__device__ __forceinline__ void mma_tf32(float* c, const unsigned* a, unsigned b0, unsigned b1) {
    asm volatile("mma.sync.aligned.m16n8k8.row.col.f32.tf32.tf32.f32 "
        "{%0,%1,%2,%3}, {%4,%5,%6,%7}, {%8,%9}, {%0,%1,%2,%3};\n"
        : "+f"(c[0]), "+f"(c[1]), "+f"(c[2]), "+f"(c[3])
        : "r"(a[0]), "r"(a[1]), "r"(a[2]), "r"(a[3]), "r"(b0), "r"(b1));
}
__device__ __forceinline__ void mma_bf16(float* c, const unsigned* a, unsigned b0, unsigned b1) {
    asm volatile("mma.sync.aligned.m16n8k16.row.col.f32.bf16.bf16.f32 "
        "{%0,%1,%2,%3}, {%4,%5,%6,%7}, {%8,%9}, {%0,%1,%2,%3};\n"
        : "+f"(c[0]), "+f"(c[1]), "+f"(c[2]), "+f"(c[3])
        : "r"(a[0]), "r"(a[1]), "r"(a[2]), "r"(a[3]), "r"(b0), "r"(b1));
}
__device__ __forceinline__ void ldmat4(unsigned* r, unsigned addr) {
    asm volatile("ldmatrix.sync.aligned.m8n8.x4.shared.b16 {%0,%1,%2,%3}, [%4];"
        : "=r"(r[0]), "=r"(r[1]), "=r"(r[2]), "=r"(r[3]) : "r"(addr));
}
__device__ __forceinline__ void cpasync16(unsigned dst, const void* src) {
    asm volatile("cp.async.cg.shared.global [%0], [%1], 16;\n" :: "r"(dst), "l"(src));
}
__device__ __forceinline__ void stcs2(float* p, float a, float b) {
    float2 v = make_float2(a, b);
    __stcs((float2*)p, v);
}

// ---- K0: fused preamble ------------------------------------------------------
__global__ void k_pre(const int* __restrict__ target, const float* __restrict__ emb,
                      const float* __restrict__ w_out, const float* __restrict__ w_ih,
                      const float* __restrict__ h0) {
    int bx = blockIdx.x;
    if (bx < cV) {
        size_t i = (size_t)bx * 1024 + threadIdx.x * 4;
        float4 v = *(const float4*)(w_out + i);
        *(__nv_bfloat162*)(g_wob + i)     = __floats2bfloat162_rn(v.x, v.y);
        *(__nv_bfloat162*)(g_wob + i + 2) = __floats2bfloat162_rn(v.z, v.w);
    } else if (bx < cV + cG) {
        size_t i = (size_t)(bx - cV) * 1024 + threadIdx.x * 4;
        float4 v = *(const float4*)(w_ih + i);
        uint4 o; o.x = f2tf(v.x); o.y = f2tf(v.y); o.z = f2tf(v.z); o.w = f2tf(v.w);
        *(uint4*)(g_wihtf + i) = o;
    } else if (bx < cV + cG + cM) {
        int m = bx - cV - cG, t = m >> 5, b = m & 31;
        int tok = (t == 0) ? 1 : target[b * cT + (t - 1)];
        float4 v = ((const float4*)(emb + (size_t)tok * cH))[threadIdx.x];
        uint4 o;
        o.x = f2tf(fmaxf(v.x, 0.f)); o.y = f2tf(fmaxf(v.y, 0.f));
        o.z = f2tf(fmaxf(v.z, 0.f)); o.w = f2tf(fmaxf(v.w, 0.f));
        ((uint4*)(g_X + (size_t)m * cH))[threadIdx.x] = o;
    } else {
        int i = (bx - cV - cG - cM) * 256 + threadIdx.x;
        g_htf[0][i] = f2tf(h0[i]);
        if (i < cM) g_sum[i] = 0.f;
        if (i < NCTA * 32) g_flags[i] = 0;
    }
}

// ---- K2: gi = X @ w_ih^T + b_ih (tf32, 128x128 tile, 3-stage, 2 CTA/SM) ------
constexpr int GKCH = 32;
constexpr int GPAD = 36;
constexpr int GSTG = 128 * GPAD * 4;       // 18432 B
constexpr int GSM_TOT = 6 * GSTG + 16;

__global__ __launch_bounds__(256, 2) void k_gi(const float* __restrict__ bih) {
    extern __shared__ char smg[];
    const unsigned smb = smem_u32(smg);
    const unsigned aBase = smb, bBase = smb + 3 * GSTG;
    const int m0 = blockIdx.x * 128, n0 = blockIdx.y * 128;
    const int tid = threadIdx.x, lane = tid & 31;
    const int w = tid >> 5, wm = w & 1, wn = w >> 1;
    const int g = lane >> 2, q = lane & 3;

    float acc[4][4][4];
#pragma unroll
    for (int a = 0; a < 4; a++)
#pragma unroll
        for (int b = 0; b < 4; b++)
#pragma unroll
            for (int c = 0; c < 4; c++) acc[a][b][c] = 0.f;

    auto loadStage = [&](int s) {
        int buf = s % 3;
        const char* asrc = (const char*)(g_X + (size_t)m0 * cH + s * GKCH);
        const char* bsrc = (const char*)(g_wihtf + (size_t)n0 * cH + s * GKCH);
        unsigned ad = aBase + buf * GSTG, bd = bBase + buf * GSTG;
#pragma unroll
        for (int j = 0; j < 4; ++j) {
            int i = tid + 256 * j;
            int row = i >> 3, cb = (i & 7) * 16;
            cpasync16(ad + row * (GPAD * 4) + cb, asrc + (size_t)row * (cH * 4) + cb);
            cpasync16(bd + row * (GPAD * 4) + cb, bsrc + (size_t)row * (cH * 4) + cb);
        }
        asm volatile("cp.async.commit_group;\n");
    };

    loadStage(0); loadStage(1);
    constexpr int NS = cH / GKCH;   // 32
    for (int s = 0; s < NS; ++s) {
        if (s == NS - 1) asm volatile("cp.async.wait_group 0;\n");
        else             asm volatile("cp.async.wait_group 1;\n");
        __syncthreads();
        if (s + 2 < NS) loadStage(s + 2);
        int buf = s % 3;
        const unsigned* aS = (const unsigned*)(smg + buf * GSTG);
        const unsigned* bS = (const unsigned*)(smg + 3 * GSTG + buf * GSTG);
#pragma unroll
        for (int kt = 0; kt < 4; ++kt) {
            int kk = kt * 8;
            unsigned a[4][4];
#pragma unroll
            for (int mt = 0; mt < 4; ++mt) {
                int r = wm * 64 + mt * 16 + g;
                a[mt][0] = aS[r * GPAD + kk + q];
                a[mt][1] = aS[(r + 8) * GPAD + kk + q];
                a[mt][2] = aS[r * GPAD + kk + q + 4];
                a[mt][3] = aS[(r + 8) * GPAD + kk + q + 4];
            }
#pragma unroll
            for (int nt = 0; nt < 4; ++nt) {
                int c = wn * 32 + nt * 8 + g;
                unsigned b0 = bS[c * GPAD + kk + q];
                unsigned b1 = bS[c * GPAD + kk + q + 4];
#pragma unroll
                for (int mt = 0; mt < 4; ++mt)
                    mma_tf32(acc[mt][nt], a[mt], b0, b1);
            }
        }
    }
#pragma unroll
    for (int mt = 0; mt < 4; ++mt)
#pragma unroll
        for (int nt = 0; nt < 4; ++nt) {
            int row = m0 + wm * 64 + mt * 16 + g;
            int col = n0 + wn * 32 + nt * 8 + 2 * q;
            float b0 = bih[col], b1 = bih[col + 1];
            g_gi[(size_t)row * cG + col]           = acc[mt][nt][0] + b0;
            g_gi[(size_t)row * cG + col + 1]       = acc[mt][nt][1] + b1;
            g_gi[(size_t)(row + 8) * cG + col]     = acc[mt][nt][2] + b0;
            g_gi[(size_t)(row + 8) * cG + col + 1] = acc[mt][nt][3] + b1;
        }
}

// ---- K3: persistent GRU recurrence (tf32, 192 threads, single acc chain) -----
constexpr int WSTR = 1028;
constexpr int HSTR = 260;     // 256 + 4 pad words

__global__ __launch_bounds__(RTHREADS) void k_rnn(const float* __restrict__ h0,
                                                  const float* __restrict__ Whh,
                                                  const float* __restrict__ bhh,
                                                  float* __restrict__ outh) {
    extern __shared__ unsigned su[];
    unsigned* w_s  = su;                        // 24 * WSTR
    unsigned* h_s  = w_s + 24 * WSTR;           // 3 * 32 * HSTR
    float*    sGH  = (float*)(h_s + 3 * 32 * HSTR);
    float*    h_own = sGH + 3 * 32 * 9;
    float*    bhh_s = h_own + 32 * 8;

    const int tid = threadIdx.x, lane = tid & 31, w = tid >> 5;
    const int gate = w >> 1, mh = w & 1;        // warp = (gate, m-half)
    const int g = lane >> 2, q = lane & 3;
    const int u0 = blockIdx.x * UPC;

    for (int i = tid; i < 24 * 256; i += RTHREADS) {
        int r = i >> 8, c4 = (i & 255) * 4;
        int gt = r >> 3, rr = r & 7;
        float4 v = *(const float4*)(Whh + ((size_t)gt * cH + u0 + rr) * cH + c4);
        unsigned* p = &w_s[r * WSTR + c4];
        p[0] = f2tf(v.x); p[1] = f2tf(v.y); p[2] = f2tf(v.z); p[3] = f2tf(v.w);
    }
    if (tid < 24) bhh_s[tid] = bhh[(tid >> 3) * cH + u0 + (tid & 7)];
    for (int i = tid; i < 32 * 8; i += RTHREADS)
        h_own[i] = h0[(i >> 3) * cH + u0 + (i & 7)];
    __syncthreads();

    for (int t = 0; t < cT; ++t) {
        float gr[2], gz[2], gn[2];
#pragma unroll
        for (int j = 0; j < 2; ++j) {
            int idx = tid + RTHREADS * j;
            if (idx < 256) {
                int b = idx >> 3, u = idx & 7;
                const float* gi = g_gi + ((size_t)t * cB + b) * cG + u0 + u;
                gr[j] = gi[0]; gz[j] = gi[cH]; gn[j] = gi[2 * cH];
            }
        }
        const unsigned* hsrc = g_htf[t & 1];
        auto ldchunk = [&](int ki) {
            int buf = ki % 3, kc = ki * 256;
            for (int i = tid; i < 2048; i += RTHREADS) {   // 32 rows x 64 uint4
                int r = i >> 6, c4 = (i & 63) * 4;
                cpasync16(smem_u32(&h_s[buf * 32 * HSTR + r * HSTR + c4]),
                          hsrc + r * cH + kc + c4);
            }
            asm volatile("cp.async.commit_group;\n");
        };
        ldchunk(0); ldchunk(1);
        float acc[4] = {0.f, 0.f, 0.f, 0.f};
        for (int ki = 0; ki < 4; ++ki) {
            if (ki == 3) asm volatile("cp.async.wait_group 0;\n");
            else         asm volatile("cp.async.wait_group 1;\n");
            __syncthreads();
            if (ki + 2 < 4) ldchunk(ki + 2);
            const unsigned* hb = &h_s[(ki % 3) * 32 * HSTR];
            const unsigned* wb = &w_s[gate * 8 * WSTR + ki * 256];
#pragma unroll
            for (int kk = 0; kk < 32; ++kk) {
                int kcol = kk * 8;
                unsigned b0 = wb[g * WSTR + kcol + q];
                unsigned b1 = wb[g * WSTR + kcol + q + 4];
                unsigned a[4];
                a[0] = hb[(mh * 16 + g) * HSTR + kcol + q];
                a[1] = hb[(mh * 16 + g + 8) * HSTR + kcol + q];
                a[2] = hb[(mh * 16 + g) * HSTR + kcol + q + 4];
                a[3] = hb[(mh * 16 + g + 8) * HSTR + kcol + q + 4];
                mma_tf32(acc, a, b0, b1);
            }
        }
        __syncthreads();
        float* sg = sGH + gate * (32 * 9);
        sg[(mh * 16 + g) * 9 + 2 * q]         = acc[0];
        sg[(mh * 16 + g) * 9 + 2 * q + 1]     = acc[1];
        sg[(mh * 16 + g + 8) * 9 + 2 * q]     = acc[2];
        sg[(mh * 16 + g + 8) * 9 + 2 * q + 1] = acc[3];
        __syncthreads();
#pragma unroll
        for (int j = 0; j < 2; ++j) {
            int idx = tid + RTHREADS * j;
            if (idx < 256) {
                int b = idx >> 3, u = idx & 7;
                float pr = gr[j] + sGH[0 * 288 + b * 9 + u] + bhh_s[u];
                float pz = gz[j] + sGH[1 * 288 + b * 9 + u] + bhh_s[8 + u];
                float hn = sGH[2 * 288 + b * 9 + u] + bhh_s[16 + u];
                float r = 1.f / (1.f + expf(-pr));
                float z = 1.f / (1.f + expf(-pz));
                float n = tanhf(gn[j] + r * hn);
                float hv = (1.f - z) * n + z * h_own[idx];
                h_own[idx] = hv;
                g_htf[(t + 1) & 1][b * cH + u0 + u] = f2tf(hv);
                g_hsb[((size_t)b * cT + t) * cH + u0 + u] = __float2bfloat16(hv);
                if (t == cT - 1) outh[b * cH + u0 + u] = hv;
            }
        }
        __threadfence();
        __syncthreads();
        if (tid == 0) ((volatile unsigned*)g_flags)[blockIdx.x * 32] = t + 1;
        if (tid < NCTA)
            while (((volatile unsigned*)g_flags)[tid * 32] < (unsigned)(t + 1)) { }
        __syncthreads();
        __threadfence();
    }
}

// ---- K4: logits GEMM (bf16 HMMA, 128x128, 3-stage cp.async, 2 CTA/SM) --------
constexpr int LKCH = 64;
constexpr int LPAD = 72;
constexpr int LSTG = 128 * LPAD * 2;      // 18432 B
constexpr int LSM_TOT = 6 * LSTG + 1024;

__global__ __launch_bounds__(256, 2) void k_logits(const float* __restrict__ bout,
                                                   float* __restrict__ out) {
    extern __shared__ char sm[];
    const unsigned smb = smem_u32(sm);
    const unsigned aBase = smb, bBase = smb + 3 * LSTG;
    float* srow  = (float*)(sm + 6 * LSTG);
    float* sbias = srow + 128;
    const int m0 = blockIdx.x * 128, n0 = blockIdx.y * 128;
    const int tid = threadIdx.x, lane = tid & 31;
    const int w = tid >> 5, wm = w & 1, wn = w >> 1;
    const int g = lane >> 2, q = lane & 3;
    const int lr = lane & 7, lh = (lane >> 3) & 1, lq = lane >> 4;
    const int arow = lr + lh * 8, acol = lq * 8;
    const int brow = lr + lq * 8, bcol = lh * 8;

    if (tid < 128) { srow[tid] = 0.f; sbias[tid] = bout[n0 + tid]; }

    float acc[4][4][4];
#pragma unroll
    for (int a = 0; a < 4; a++)
#pragma unroll
        for (int b = 0; b < 4; b++)
#pragma unroll
            for (int c = 0; c < 4; c++) acc[a][b][c] = 0.f;

    auto loadStage = [&](int s) {
        int buf = s % 3;
        const char* asrc = (const char*)(g_hsb + (size_t)m0 * cH + s * LKCH);
        const char* bsrc = (const char*)(g_wob + (size_t)n0 * cH + s * LKCH);
        unsigned ad = aBase + buf * LSTG, bd = bBase + buf * LSTG;
#pragma unroll
        for (int j = 0; j < 4; ++j) {
            int i = tid + 256 * j;
            int row = i >> 3, cb = (i & 7) * 16;
            cpasync16(ad + row * (LPAD * 2) + cb, asrc + (size_t)row * (cH * 2) + cb);
            cpasync16(bd + row * (LPAD * 2) + cb, bsrc + (size_t)row * (cH * 2) + cb);
        }
        asm volatile("cp.async.commit_group;\n");
    };

    loadStage(0); loadStage(1);
    constexpr int NS = cH / LKCH;   // 16
    for (int s = 0; s < NS; ++s) {
        if (s == NS - 1) asm volatile("cp.async.wait_group 0;\n");
        else             asm volatile("cp.async.wait_group 1;\n");
        __syncthreads();
        if (s + 2 < NS) loadStage(s + 2);
        int buf = s % 3;
        unsigned aS = aBase + buf * LSTG, bS = bBase + buf * LSTG;
#pragma unroll
        for (int kt = 0; kt < 4; ++kt) {
            int kk = kt * 16;
            unsigned a[4][4], bf[2][4];
#pragma unroll
            for (int mt = 0; mt < 4; ++mt)
                ldmat4(a[mt], aS + (((wm * 64 + mt * 16 + arow) * LPAD + kk + acol) << 1));
#pragma unroll
            for (int p = 0; p < 2; ++p)
                ldmat4(bf[p], bS + (((wn * 32 + p * 16 + brow) * LPAD + kk + bcol) << 1));
#pragma unroll
            for (int nt = 0; nt < 4; ++nt) {
                unsigned b0 = bf[nt >> 1][(nt & 1) * 2];
                unsigned b1 = bf[nt >> 1][(nt & 1) * 2 + 1];
#pragma unroll
                for (int mt = 0; mt < 4; ++mt)
                    mma_bf16(acc[mt][nt], a[mt], b0, b1);
            }
        }
    }

    // epilogue: bias + streaming float2 stores + exp partial sums
    float es[4][2];
#pragma unroll
    for (int mt = 0; mt < 4; ++mt) { es[mt][0] = 0.f; es[mt][1] = 0.f; }
#pragma unroll
    for (int mt = 0; mt < 4; ++mt)
#pragma unroll
        for (int nt = 0; nt < 4; ++nt) {
            int row = m0 + wm * 64 + mt * 16 + g;
            int lc  = wn * 32 + nt * 8 + 2 * q;
            int col = n0 + lc;
            float v0 = acc[mt][nt][0] + sbias[lc];
            float v1 = acc[mt][nt][1] + sbias[lc + 1];
            float v2 = acc[mt][nt][2] + sbias[lc];
            float v3 = acc[mt][nt][3] + sbias[lc + 1];
            stcs2(out + (size_t)row * cV + col, v0, v1);
            stcs2(out + (size_t)(row + 8) * cV + col, v2, v3);
            es[mt][0] += __expf(v0) + __expf(v1);
            es[mt][1] += __expf(v2) + __expf(v3);
        }
#pragma unroll
    for (int mt = 0; mt < 4; ++mt)
#pragma unroll
        for (int h = 0; h < 2; ++h) {
            es[mt][h] += __shfl_xor_sync(0xFFFFFFFFu, es[mt][h], 1);
            es[mt][h] += __shfl_xor_sync(0xFFFFFFFFu, es[mt][h], 2);
        }
    if (q == 0) {
#pragma unroll
        for (int mt = 0; mt < 4; ++mt) {
            atomicAdd(&srow[wm * 64 + mt * 16 + g], es[mt][0]);
            atomicAdd(&srow[wm * 64 + mt * 16 + g + 8], es[mt][1]);
        }
    }
    __syncthreads();
    if (tid < 128) atomicAdd(&g_sum[m0 + tid], srow[tid]);
}

// ---- K6: subtract log(sum) in-place, streaming (8 CTAs per row) --------------
__global__ __launch_bounds__(256) void k_sub(float* __restrict__ out) {
    int row = blockIdx.x;
    float l = logf(g_sum[row]);
    const int seg = blockIdx.y;              // 0..7, 4000 elems each
    float4* p = (float4*)(out + (size_t)row * cV + seg * 4000);
    for (int i = threadIdx.x; i < 1000; i += 256) {
        float4 v = __ldcs(p + i);
        v.x -= l; v.y -= l; v.z -= l; v.w -= l;
        __stcs(p + i, v);
    }
}

extern "C" void kernel_launch(void* const* d_in, const int* in_sizes, int n_in,
                              void* d_out, int out_size) {
    const float* enc_hidden = (const float*)d_in[1];
    const int*   target     = (const int*)d_in[2];
    const float* emb        = (const float*)d_in[3];
    const float* w_ih       = (const float*)d_in[4];
    const float* w_hh       = (const float*)d_in[5];
    const float* b_ih       = (const float*)d_in[6];
    const float* b_hh       = (const float*)d_in[7];
    const float* w_out      = (const float*)d_in[8];
    const float* b_out      = (const float*)d_in[9];
    float* out = (float*)d_out;

    constexpr int RSMEM = (24 * WSTR + 3 * 32 * HSTR) * 4 + (3 * 32 * 9 + 32 * 8 + 24) * 4;
    cudaFuncSetAttribute(k_rnn, cudaFuncAttributeMaxDynamicSharedMemorySize, RSMEM);
    cudaFuncSetAttribute(k_logits, cudaFuncAttributeMaxDynamicSharedMemorySize, LSM_TOT);
    cudaFuncSetAttribute(k_gi, cudaFuncAttributeMaxDynamicSharedMemorySize, GSM_TOT);

    k_pre<<<cV + cG + cM + cB * cH / 256, 256>>>(target, emb, w_out, w_ih, enc_hidden);
    k_gi<<<dim3(cM / 128, cG / 128), 256, GSM_TOT>>>(b_ih);
    k_rnn<<<NCTA, RTHREADS, RSMEM>>>(enc_hidden, w_hh, b_hh, out + cBTV);
    k_logits<<<dim3(cM / 128, cV / 128), 256, LSM_TOT>>>(b_out, out);
    k_sub<<<dim3(cM, 8), 256>>>(out);
}